// round 1
// baseline (speedup 1.0000x reference)
#include <cuda_runtime.h>

#define B_ 128
#define N_ 1024
#define E_ 16384
#define ENTITY_ 100000
#define HID_ 100
#define G3 300

// Scratch (static __device__ per harness rules; no runtime allocation)
__device__ float g_T[ENTITY_ * HID_];        // emb_table @ gcn_w   (40MB)
__device__ float g_seq[B_ * N_ * HID_];      // GCN output          (52MB)
__device__ float g_GX[B_ * N_ * G3];         // seq @ w_ih^T + b_ih (157MB)
__device__ int   g_soff[B_ * (N_ + 1)];
__device__ int   g_scol[B_ * E_];
__device__ float g_sval[B_ * E_];

typedef unsigned long long u64;

__device__ __forceinline__ void ffma2(u64 &acc, u64 a, u64 b) {
    asm("fma.rn.f32x2 %0, %1, %2, %0;" : "+l"(acc) : "l"(a), "l"(b));
}
__device__ __forceinline__ u64 pk2(float lo, float hi) {
    u64 r; asm("mov.b64 %0, {%1, %2};" : "=l"(r) : "f"(lo), "f"(hi)); return r;
}
__device__ __forceinline__ float sum2(u64 v) {
    float lo, hi; asm("mov.b64 {%0, %1}, %2;" : "=f"(lo), "=f"(hi) : "l"(v)); return lo + hi;
}
__device__ __forceinline__ void cp4(void* s, const void* g) {
    unsigned a = (unsigned)__cvta_generic_to_shared(s);
    asm volatile("cp.async.ca.shared.global [%0], [%1], 4;" :: "r"(a), "l"(g));
}

// ---------------------------------------------------------------------------
// K1: T = emb_table @ gcn_w   [100000,100] @ [100,100]
// block = 128 threads (thread h computes column h), 64 rows per block.
// Weights column h live in registers as 50 f32x2 pairs (packed along K).
// ---------------------------------------------------------------------------
__global__ __launch_bounds__(128) void k1_T(const float* __restrict__ emb,
                                            const float* __restrict__ gcn_w) {
    __shared__ __align__(16) float xs[64 * HID_];
    int r0 = blockIdx.x * 64;
    int rows = min(64, ENTITY_ - r0);
    int tid = threadIdx.x;
    int h = tid;
    bool act = h < HID_;
    u64 w2[50];
    if (act) {
        #pragma unroll
        for (int p = 0; p < 50; p++)
            w2[p] = pk2(gcn_w[(2 * p) * HID_ + h], gcn_w[(2 * p + 1) * HID_ + h]);
    }
    const float4* src = (const float4*)(emb + (size_t)r0 * HID_);
    float4* dst = (float4*)xs;
    int n4 = rows * 25;
    for (int i = tid; i < n4; i += 128) dst[i] = src[i];
    __syncthreads();
    if (!act) return;
    for (int m = 0; m < rows; m++) {
        const ulonglong2* xp = (const ulonglong2*)(xs + m * HID_);
        u64 a0 = 0, a1 = 0, a2 = 0, a3 = 0;
        #pragma unroll
        for (int q = 0; q < 25; q++) {
            ulonglong2 hv = xp[q];
            if (q & 1) { ffma2(a2, w2[2 * q], hv.x); ffma2(a3, w2[2 * q + 1], hv.y); }
            else       { ffma2(a0, w2[2 * q], hv.x); ffma2(a1, w2[2 * q + 1], hv.y); }
        }
        g_T[(size_t)(r0 + m) * HID_ + h] = sum2(a0) + sum2(a1) + sum2(a2) + sum2(a3);
    }
}

// ---------------------------------------------------------------------------
// K2: per-batch counting sort of edges by row (histogram + scan + scatter)
// one block (1024 threads) per batch element
// ---------------------------------------------------------------------------
__global__ __launch_bounds__(1024) void k2_sort(const int* __restrict__ row,
                                                const int* __restrict__ col,
                                                const float* __restrict__ val) {
    __shared__ int bins[N_];
    __shared__ int sA[N_];
    int b = blockIdx.x, tid = threadIdx.x;
    bins[tid] = 0;
    __syncthreads();
    const int* rb = row + b * E_;
    const int* cb = col + b * E_;
    const float* vb = val + b * E_;
    for (int e = tid; e < E_; e += 1024) atomicAdd(&bins[rb[e]], 1);
    __syncthreads();
    int cnt = bins[tid];
    sA[tid] = cnt;
    __syncthreads();
    for (int off = 1; off < N_; off <<= 1) {
        int t = (tid >= off) ? sA[tid - off] : 0;
        __syncthreads();
        sA[tid] += t;
        __syncthreads();
    }
    int excl = sA[tid] - cnt;
    g_soff[b * (N_ + 1) + tid] = excl;
    if (tid == 0) g_soff[b * (N_ + 1) + N_] = E_;
    bins[tid] = excl;
    __syncthreads();
    for (int e = tid; e < E_; e += 1024) {
        int r = rb[e];
        int pos = atomicAdd(&bins[r], 1);
        g_scol[b * E_ + pos] = cb[e];
        g_sval[b * E_ + pos] = vb[e];
    }
}

// ---------------------------------------------------------------------------
// K3: seq[b,r,:] = sum_e val * T[neighbors[b, col_e], :] + gcn_b
// one warp per (b, row); grid (128, 16) x 256 threads for occupancy
// ---------------------------------------------------------------------------
__global__ __launch_bounds__(256) void k3_agg(const int* __restrict__ nbr,
                                              const float* __restrict__ gcn_b) {
    int b = blockIdx.x;
    int rbase = blockIdx.y * 64;
    int warp = threadIdx.x >> 5, lane = threadIdx.x & 31;
    const int* sc = g_scol + b * E_;
    const float* sv = g_sval + b * E_;
    const int* nb = nbr + b * N_;
    for (int r = rbase + warp; r < rbase + 64; r += 8) {
        int beg = g_soff[b * (N_ + 1) + r], end = g_soff[b * (N_ + 1) + r + 1];
        float a0 = 0.f, a1 = 0.f, a2 = 0.f, a3 = 0.f;
        for (int ch = beg; ch < end; ch += 32) {
            int e = ch + lane;
            int c = 0; float v = 0.f;
            if (e < end) { c = sc[e]; v = sv[e]; }
            int ent = nb[c];
            int cnt = min(32, end - ch);
            for (int i = 0; i < cnt; i++) {
                int eb = __shfl_sync(0xffffffffu, ent, i);
                float vv = __shfl_sync(0xffffffffu, v, i);
                const float* tr = g_T + (size_t)eb * HID_;
                a0 += vv * tr[lane];
                a1 += vv * tr[32 + lane];
                a2 += vv * tr[64 + lane];
                a3 += vv * tr[96 + (lane & 3)];
            }
        }
        float* o = g_seq + (size_t)(b * N_ + r) * HID_;
        o[lane]      = a0 + gcn_b[lane];
        o[32 + lane] = a1 + gcn_b[32 + lane];
        o[64 + lane] = a2 + gcn_b[64 + lane];
        if (lane < 4) o[96 + lane] = a3 + gcn_b[96 + lane];
    }
}

// ---------------------------------------------------------------------------
// K4: GX = seq @ w_ih^T + b_ih   [131072,100] @ [100,300]^T
// 148 persistent blocks of 320 threads; thread j holds w_ih row j in regs.
// seq tile (64 rows) staged in smem, broadcast-read by all threads.
// ---------------------------------------------------------------------------
__global__ __launch_bounds__(320) void k4_gx(const float* __restrict__ w_ih,
                                             const float* __restrict__ b_ih) {
    __shared__ __align__(16) float xs[64 * HID_];
    int tid = threadIdx.x;
    int j = tid;
    bool act = j < G3;
    u64 w2[50];
    float bih = 0.f;
    if (act) {
        const u64* wp = (const u64*)(w_ih + j * HID_);
        #pragma unroll
        for (int p = 0; p < 50; p++) w2[p] = wp[p];
        bih = b_ih[j];
    }
    for (int tile = blockIdx.x; tile < 2048; tile += gridDim.x) {
        const float4* src = (const float4*)(g_seq + (size_t)tile * 64 * HID_);
        float4* dst = (float4*)xs;
        __syncthreads();   // previous tile fully consumed
        for (int i = tid; i < 1600; i += 320) dst[i] = src[i];
        __syncthreads();
        if (act) {
            float* o = g_GX + (size_t)tile * 64 * G3 + j;
            for (int m = 0; m < 64; m++) {
                const ulonglong2* xp = (const ulonglong2*)(xs + m * HID_);
                u64 a0 = 0, a1 = 0, a2 = 0, a3 = 0;
                #pragma unroll
                for (int q = 0; q < 25; q++) {
                    ulonglong2 hv = xp[q];
                    if (q & 1) { ffma2(a2, w2[2 * q], hv.x); ffma2(a3, w2[2 * q + 1], hv.y); }
                    else       { ffma2(a0, w2[2 * q], hv.x); ffma2(a1, w2[2 * q + 1], hv.y); }
                }
                o[m * G3] = sum2(a0) + sum2(a1) + sum2(a2) + sum2(a3) + bih;
            }
        }
    }
}

// ---------------------------------------------------------------------------
// K5: GRU recurrence, one block per batch element. 1024 serial steps.
// Thread j<300 holds w_hh row j in regs; h in smem (double-buffered);
// GX streamed through an 8-slot cp.async ring (prefetch distance 4).
// Final FC+ReLU fused at the end.
// ---------------------------------------------------------------------------
__global__ __launch_bounds__(320) void k5_gru(const float* __restrict__ w_hh,
                                              const float* __restrict__ b_hh,
                                              const float* __restrict__ fc1_w,
                                              const float* __restrict__ fc1_b,
                                              float* __restrict__ out) {
    __shared__ __align__(16) float hbuf[2][128];
    __shared__ float ghs[G3];
    __shared__ float ring[8][G3];
    int b = blockIdx.x, tid = threadIdx.x;
    int j = tid;
    bool act = j < G3;
    u64 w2[50];
    float bhh = 0.f;
    if (act) {
        const u64* wp = (const u64*)(w_hh + j * HID_);
        #pragma unroll
        for (int p = 0; p < 50; p++) w2[p] = wp[p];
        bhh = b_hh[j];
    }
    if (tid < 128) { hbuf[0][tid] = 0.f; hbuf[1][tid] = 0.f; }
    const float* gxb = g_GX + (size_t)b * N_ * G3;
    #pragma unroll
    for (int p = 0; p < 4; p++) {
        if (act) cp4(&ring[p][j], gxb + p * G3 + j);
        asm volatile("cp.async.commit_group;");
    }
    for (int t = 0; t < N_; t++) {
        asm volatile("cp.async.wait_group 3;");
        __syncthreads();                         // stage t data + new h visible
        int pf = t + 4;
        if (act && pf < N_) cp4(&ring[pf & 7][j], gxb + (size_t)pf * G3 + j);
        asm volatile("cp.async.commit_group;");
        const float* hc = hbuf[t & 1];
        if (act) {
            const ulonglong2* hp = (const ulonglong2*)hc;
            u64 a0 = 0, a1 = 0, a2 = 0, a3 = 0;
            #pragma unroll
            for (int q = 0; q < 25; q++) {
                ulonglong2 hv = hp[q];
                if (q & 1) { ffma2(a2, w2[2 * q], hv.x); ffma2(a3, w2[2 * q + 1], hv.y); }
                else       { ffma2(a0, w2[2 * q], hv.x); ffma2(a1, w2[2 * q + 1], hv.y); }
            }
            ghs[j] = sum2(a0) + sum2(a1) + sum2(a2) + sum2(a3) + bhh;
        }
        __syncthreads();                         // ghs ready
        if (j < HID_) {
            int st = t & 7;
            float gxr = ring[st][j], gxz = ring[st][HID_ + j], gxn = ring[st][2 * HID_ + j];
            float hr = ghs[j], hz = ghs[HID_ + j], hn = ghs[2 * HID_ + j];
            float r = 1.f / (1.f + expf(-(gxr + hr)));
            float z = 1.f / (1.f + expf(-(gxz + hz)));
            float n = tanhf(gxn + r * hn);
            hbuf[(t + 1) & 1][j] = (1.f - z) * n + z * hc[j];
        }
    }
    __syncthreads();
    if (j < HID_) {
        const float* hf = hbuf[0];               // final h (t=1023 wrote buf 0)
        float acc = fc1_b[j];
        const float* wr = fc1_w + j * HID_;
        #pragma unroll
        for (int k = 0; k < HID_; k++) acc += hf[k] * wr[k];
        out[b * HID_ + j] = fmaxf(acc, 0.f);
    }
}

// ---------------------------------------------------------------------------
extern "C" void kernel_launch(void* const* d_in, const int* in_sizes, int n_in,
                              void* d_out, int out_size) {
    const int*   neighbors = (const int*)d_in[0];
    const int*   adj_row   = (const int*)d_in[1];
    const int*   adj_col   = (const int*)d_in[2];
    const float* adj_val   = (const float*)d_in[3];
    const float* emb       = (const float*)d_in[4];
    const float* gcn_w     = (const float*)d_in[5];
    const float* gcn_b     = (const float*)d_in[6];
    const float* w_ih      = (const float*)d_in[7];
    const float* w_hh      = (const float*)d_in[8];
    const float* b_ih      = (const float*)d_in[9];
    const float* b_hh      = (const float*)d_in[10];
    const float* fc1_w     = (const float*)d_in[11];
    const float* fc1_b     = (const float*)d_in[12];
    float* out = (float*)d_out;

    k1_T   <<<(ENTITY_ + 63) / 64, 128>>>(emb, gcn_w);
    k2_sort<<<B_, 1024>>>(adj_row, adj_col, adj_val);
    k3_agg <<<dim3(B_, 16), 256>>>(neighbors, gcn_b);
    k4_gx  <<<148, 320>>>(w_ih, b_ih);
    k5_gru <<<B_, 320>>>(w_hh, b_hh, fc1_w, fc1_b, out);
}

// round 2
// speedup vs baseline: 1.1162x; 1.1162x over previous
#include <cuda_runtime.h>

#define B_ 128
#define N_ 1024
#define E_ 16384
#define ENTITY_ 100000
#define HID_ 100
#define G3 300

// Scratch (static __device__ per harness rules; no runtime allocation)
__device__ float g_T[ENTITY_ * HID_];        // emb_table @ gcn_w   (40MB)
__device__ float g_seq[B_ * N_ * HID_];      // GCN output          (52MB)
__device__ float g_GX[B_ * N_ * G3];         // seq @ w_ih^T + b_ih (157MB)
__device__ int   g_soff[B_ * (N_ + 1)];
__device__ int   g_scol[B_ * E_];
__device__ float g_sval[B_ * E_];

typedef unsigned long long u64;

__device__ __forceinline__ void ffma2(u64 &acc, u64 a, u64 b) {
    asm("fma.rn.f32x2 %0, %1, %2, %0;" : "+l"(acc) : "l"(a), "l"(b));
}
__device__ __forceinline__ u64 pk2(float lo, float hi) {
    u64 r; asm("mov.b64 %0, {%1, %2};" : "=l"(r) : "f"(lo), "f"(hi)); return r;
}
__device__ __forceinline__ float sum2(u64 v) {
    float lo, hi; asm("mov.b64 {%0, %1}, %2;" : "=f"(lo), "=f"(hi) : "l"(v)); return lo + hi;
}
__device__ __forceinline__ void cp4(void* s, const void* g) {
    unsigned a = (unsigned)__cvta_generic_to_shared(s);
    asm volatile("cp.async.ca.shared.global [%0], [%1], 4;" :: "r"(a), "l"(g));
}

// ---------------------------------------------------------------------------
// K1: T = emb_table @ gcn_w   [100000,100] @ [100,100]
// 2-j x k-half scheme: thread = (khalf, j0); computes cols j0 and j0+50 over
// k in [52h, 52h+52) (zero-padded). 16B x-broadcast feeds 4 FFMA2.
// ---------------------------------------------------------------------------
__global__ __launch_bounds__(128) void k1_T(const float* __restrict__ emb,
                                            const float* __restrict__ gcn_w) {
    __shared__ __align__(16) float xs[64 * 104];
    __shared__ float ps[2][8][104];
    int tid = threadIdx.x;
    int h = tid >> 6;          // k-half 0/1
    int j0 = tid & 63;         // <50 active
    bool act = j0 < 50;
    int jA = j0, jB = j0 + 50;
    u64 wA[26], wB[26];
    if (act) {
        #pragma unroll
        for (int p = 0; p < 26; p++) {
            int k = 52 * h + 2 * p;
            if (k + 1 < HID_) {
                wA[p] = pk2(gcn_w[k * HID_ + jA], gcn_w[(k + 1) * HID_ + jA]);
                wB[p] = pk2(gcn_w[k * HID_ + jB], gcn_w[(k + 1) * HID_ + jB]);
            } else { wA[p] = 0ull; wB[p] = 0ull; }
        }
    }
    int r0 = blockIdx.x * 64;
    int rows = min(64, ENTITY_ - r0);
    const float4* src = (const float4*)(emb + (size_t)r0 * HID_);
    for (int i = tid; i < 64 * 26; i += 128) {
        int m = i / 26, c = i % 26;
        float4 v = make_float4(0.f, 0.f, 0.f, 0.f);
        if (c < 25 && m < rows) v = src[m * 25 + c];
        *(float4*)(xs + m * 104 + c * 4) = v;
    }
    __syncthreads();
    for (int chunk = 0; chunk < 8; chunk++) {
        int m0 = chunk * 8;
        if (act) {
            u64 aA[8], aB[8];
            #pragma unroll
            for (int mm = 0; mm < 8; mm++) { aA[mm] = 0; aB[mm] = 0; }
            #pragma unroll
            for (int mm = 0; mm < 8; mm++) {
                const ulonglong2* xp = (const ulonglong2*)(xs + (m0 + mm) * 104 + 52 * h);
                #pragma unroll
                for (int c = 0; c < 13; c++) {
                    ulonglong2 hv = xp[c];
                    ffma2(aA[mm], wA[2 * c], hv.x);
                    ffma2(aA[mm], wA[2 * c + 1], hv.y);
                    ffma2(aB[mm], wB[2 * c], hv.x);
                    ffma2(aB[mm], wB[2 * c + 1], hv.y);
                }
            }
            #pragma unroll
            for (int mm = 0; mm < 8; mm++) {
                ps[h][mm][jA] = sum2(aA[mm]);
                ps[h][mm][jB] = sum2(aB[mm]);
            }
        }
        __syncthreads();
        for (int o = tid; o < 8 * HID_; o += 128) {
            int mm = o / HID_, j = o % HID_;
            int m = m0 + mm;
            if (m < rows)
                g_T[(size_t)(r0 + m) * HID_ + j] = ps[0][mm][j] + ps[1][mm][j];
        }
        __syncthreads();
    }
}

// ---------------------------------------------------------------------------
// K2: per-batch counting sort of edges by row (histogram + scan + scatter)
// ---------------------------------------------------------------------------
__global__ __launch_bounds__(1024) void k2_sort(const int* __restrict__ row,
                                                const int* __restrict__ col,
                                                const float* __restrict__ val) {
    __shared__ int bins[N_];
    __shared__ int sA[N_];
    int b = blockIdx.x, tid = threadIdx.x;
    bins[tid] = 0;
    __syncthreads();
    const int* rb = row + b * E_;
    const int* cb = col + b * E_;
    const float* vb = val + b * E_;
    for (int e = tid; e < E_; e += 1024) atomicAdd(&bins[rb[e]], 1);
    __syncthreads();
    int cnt = bins[tid];
    sA[tid] = cnt;
    __syncthreads();
    for (int off = 1; off < N_; off <<= 1) {
        int t = (tid >= off) ? sA[tid - off] : 0;
        __syncthreads();
        sA[tid] += t;
        __syncthreads();
    }
    int excl = sA[tid] - cnt;
    g_soff[b * (N_ + 1) + tid] = excl;
    if (tid == 0) g_soff[b * (N_ + 1) + N_] = E_;
    bins[tid] = excl;
    __syncthreads();
    for (int e = tid; e < E_; e += 1024) {
        int r = rb[e];
        int pos = atomicAdd(&bins[r], 1);
        g_scol[b * E_ + pos] = cb[e];
        g_sval[b * E_ + pos] = vb[e];
    }
}

// ---------------------------------------------------------------------------
// K3: seq[b,r,:] = sum_e val * T[neighbors[b, col_e], :] + gcn_b
// one warp per (b, row); 2-edge unroll for MLP
// ---------------------------------------------------------------------------
__global__ __launch_bounds__(256) void k3_agg(const int* __restrict__ nbr,
                                              const float* __restrict__ gcn_b) {
    int b = blockIdx.x;
    int rbase = blockIdx.y * 64;
    int warp = threadIdx.x >> 5, lane = threadIdx.x & 31;
    const int* sc = g_scol + b * E_;
    const float* sv = g_sval + b * E_;
    const int* nb = nbr + b * N_;
    for (int r = rbase + warp; r < rbase + 64; r += 8) {
        int beg = g_soff[b * (N_ + 1) + r], end = g_soff[b * (N_ + 1) + r + 1];
        float a0 = 0.f, a1 = 0.f, a2 = 0.f, a3 = 0.f;
        float c0 = 0.f, c1 = 0.f, c2 = 0.f, c3 = 0.f;
        for (int ch = beg; ch < end; ch += 32) {
            int e = ch + lane;
            int c = 0; float v = 0.f;
            if (e < end) { c = sc[e]; v = sv[e]; }
            int ent = nb[c];
            int cnt = min(32, end - ch);
            int i = 0;
            for (; i + 1 < cnt; i += 2) {
                int e0 = __shfl_sync(0xffffffffu, ent, i);
                int e1 = __shfl_sync(0xffffffffu, ent, i + 1);
                float v0 = __shfl_sync(0xffffffffu, v, i);
                float v1 = __shfl_sync(0xffffffffu, v, i + 1);
                const float* t0 = g_T + (size_t)e0 * HID_;
                const float* t1 = g_T + (size_t)e1 * HID_;
                float x0 = t0[lane], x1 = t0[32 + lane], x2 = t0[64 + lane], x3 = t0[96 + (lane & 3)];
                float y0 = t1[lane], y1 = t1[32 + lane], y2 = t1[64 + lane], y3 = t1[96 + (lane & 3)];
                a0 += v0 * x0; a1 += v0 * x1; a2 += v0 * x2; a3 += v0 * x3;
                c0 += v1 * y0; c1 += v1 * y1; c2 += v1 * y2; c3 += v1 * y3;
            }
            if (i < cnt) {
                int e0 = __shfl_sync(0xffffffffu, ent, i);
                float v0 = __shfl_sync(0xffffffffu, v, i);
                const float* t0 = g_T + (size_t)e0 * HID_;
                a0 += v0 * t0[lane];
                a1 += v0 * t0[32 + lane];
                a2 += v0 * t0[64 + lane];
                a3 += v0 * t0[96 + (lane & 3)];
            }
        }
        float* o = g_seq + (size_t)(b * N_ + r) * HID_;
        o[lane]      = a0 + c0 + gcn_b[lane];
        o[32 + lane] = a1 + c1 + gcn_b[32 + lane];
        o[64 + lane] = a2 + c2 + gcn_b[64 + lane];
        if (lane < 4) o[96 + lane] = a3 + c3 + gcn_b[96 + lane];
    }
}

// ---------------------------------------------------------------------------
// K4: GX = seq @ w_ih^T + b_ih   [131072,100] @ [100,300]^T
// 2-j x k-half scheme: thread = (khalf, j0<150); computes cols j0, j0+150
// over k in [52h, 52h+52). Each 16B x-broadcast feeds 4 FFMA2 (halved L1
// pressure vs round 1); 16 accumulator chains per thread for ILP.
// ---------------------------------------------------------------------------
__global__ __launch_bounds__(320) void k4_gx(const float* __restrict__ w_ih,
                                             const float* __restrict__ b_ih) {
    __shared__ __align__(16) float xs[64 * 104];
    __shared__ float ps[2][8][304];
    __shared__ float bs[G3];
    int tid = threadIdx.x;
    int h = tid / 160;         // k-half
    int j0 = tid % 160;        // <150 active
    bool act = j0 < 150;
    int jA = j0, jB = j0 + 150;
    u64 wA[26], wB[26];
    if (act) {
        #pragma unroll
        for (int p = 0; p < 26; p++) {
            int k = 52 * h + 2 * p;
            if (k + 1 < HID_) {
                wA[p] = *(const u64*)(w_ih + jA * HID_ + k);
                wB[p] = *(const u64*)(w_ih + jB * HID_ + k);
            } else { wA[p] = 0ull; wB[p] = 0ull; }
        }
    }
    for (int i = tid; i < G3; i += 320) bs[i] = b_ih[i];
    for (int tile = blockIdx.x; tile < 2048; tile += gridDim.x) {
        __syncthreads();
        const float4* src = (const float4*)(g_seq + (size_t)tile * 64 * HID_);
        for (int i = tid; i < 64 * 26; i += 320) {
            int m = i / 26, c = i % 26;
            float4 v = make_float4(0.f, 0.f, 0.f, 0.f);
            if (c < 25) v = src[m * 25 + c];
            *(float4*)(xs + m * 104 + c * 4) = v;
        }
        __syncthreads();
        for (int chunk = 0; chunk < 8; chunk++) {
            int m0 = chunk * 8;
            if (act) {
                u64 aA[8], aB[8];
                #pragma unroll
                for (int mm = 0; mm < 8; mm++) { aA[mm] = 0; aB[mm] = 0; }
                #pragma unroll
                for (int mm = 0; mm < 8; mm++) {
                    const ulonglong2* xp = (const ulonglong2*)(xs + (m0 + mm) * 104 + 52 * h);
                    #pragma unroll
                    for (int c = 0; c < 13; c++) {
                        ulonglong2 hv = xp[c];
                        ffma2(aA[mm], wA[2 * c], hv.x);
                        ffma2(aA[mm], wA[2 * c + 1], hv.y);
                        ffma2(aB[mm], wB[2 * c], hv.x);
                        ffma2(aB[mm], wB[2 * c + 1], hv.y);
                    }
                }
                #pragma unroll
                for (int mm = 0; mm < 8; mm++) {
                    ps[h][mm][jA] = sum2(aA[mm]);
                    ps[h][mm][jB] = sum2(aB[mm]);
                }
            }
            __syncthreads();
            float* ob = g_GX + ((size_t)tile * 64 + m0) * G3;
            for (int o = tid; o < 8 * G3; o += 320) {
                int mm = o / G3, j = o % G3;
                ob[mm * G3 + j] = ps[0][mm][j] + ps[1][mm][j] + bs[j];
            }
            __syncthreads();
        }
    }
}

// ---------------------------------------------------------------------------
// K5: GRU recurrence, one block per batch element; fast MUFU activations.
// ---------------------------------------------------------------------------
__global__ __launch_bounds__(320) void k5_gru(const float* __restrict__ w_hh,
                                              const float* __restrict__ b_hh,
                                              const float* __restrict__ fc1_w,
                                              const float* __restrict__ fc1_b,
                                              float* __restrict__ out) {
    __shared__ __align__(16) float hbuf[2][128];
    __shared__ float ghs[G3];
    __shared__ float ring[8][G3];
    int b = blockIdx.x, tid = threadIdx.x;
    int j = tid;
    bool act = j < G3;
    u64 w2[50];
    float bhh = 0.f;
    if (act) {
        const u64* wp = (const u64*)(w_hh + j * HID_);
        #pragma unroll
        for (int p = 0; p < 50; p++) w2[p] = wp[p];
        bhh = b_hh[j];
    }
    if (tid < 128) { hbuf[0][tid] = 0.f; hbuf[1][tid] = 0.f; }
    const float* gxb = g_GX + (size_t)b * N_ * G3;
    #pragma unroll
    for (int p = 0; p < 4; p++) {
        if (act) cp4(&ring[p][j], gxb + p * G3 + j);
        asm volatile("cp.async.commit_group;");
    }
    for (int t = 0; t < N_; t++) {
        asm volatile("cp.async.wait_group 3;");
        __syncthreads();                         // stage t data + new h visible
        int pf = t + 4;
        if (act && pf < N_) cp4(&ring[pf & 7][j], gxb + (size_t)pf * G3 + j);
        asm volatile("cp.async.commit_group;");
        const float* hc = hbuf[t & 1];
        if (act) {
            const ulonglong2* hp = (const ulonglong2*)hc;
            u64 a0 = 0, a1 = 0, a2 = 0, a3 = 0;
            #pragma unroll
            for (int q = 0; q < 25; q++) {
                ulonglong2 hv = hp[q];
                if (q & 1) { ffma2(a2, w2[2 * q], hv.x); ffma2(a3, w2[2 * q + 1], hv.y); }
                else       { ffma2(a0, w2[2 * q], hv.x); ffma2(a1, w2[2 * q + 1], hv.y); }
            }
            ghs[j] = sum2(a0) + sum2(a1) + sum2(a2) + sum2(a3) + bhh;
        }
        __syncthreads();                         // ghs ready
        if (j < HID_) {
            int st = t & 7;
            float gxr = ring[st][j], gxz = ring[st][HID_ + j], gxn = ring[st][2 * HID_ + j];
            float hr = ghs[j], hz = ghs[HID_ + j], hn = ghs[2 * HID_ + j];
            float er = __expf(-(gxr + hr));
            float r = __fdividef(1.f, 1.f + er);
            float ez = __expf(-(gxz + hz));
            float z = __fdividef(1.f, 1.f + ez);
            float an = gxn + r * hn;
            float e2 = __expf(2.f * an);
            float n = 1.f - __fdividef(2.f, e2 + 1.f);
            hbuf[(t + 1) & 1][j] = (1.f - z) * n + z * hc[j];
        }
    }
    __syncthreads();
    if (j < HID_) {
        const float* hf = hbuf[0];               // final h (t=1023 wrote buf 0)
        float acc = fc1_b[j];
        const float* wr = fc1_w + j * HID_;
        #pragma unroll
        for (int k = 0; k < HID_; k++) acc += hf[k] * wr[k];
        out[b * HID_ + j] = fmaxf(acc, 0.f);
    }
}

// ---------------------------------------------------------------------------
extern "C" void kernel_launch(void* const* d_in, const int* in_sizes, int n_in,
                              void* d_out, int out_size) {
    const int*   neighbors = (const int*)d_in[0];
    const int*   adj_row   = (const int*)d_in[1];
    const int*   adj_col   = (const int*)d_in[2];
    const float* adj_val   = (const float*)d_in[3];
    const float* emb       = (const float*)d_in[4];
    const float* gcn_w     = (const float*)d_in[5];
    const float* gcn_b     = (const float*)d_in[6];
    const float* w_ih      = (const float*)d_in[7];
    const float* w_hh      = (const float*)d_in[8];
    const float* b_ih      = (const float*)d_in[9];
    const float* b_hh      = (const float*)d_in[10];
    const float* fc1_w     = (const float*)d_in[11];
    const float* fc1_b     = (const float*)d_in[12];
    float* out = (float*)d_out;

    k1_T   <<<(ENTITY_ + 63) / 64, 128>>>(emb, gcn_w);
    k2_sort<<<B_, 1024>>>(adj_row, adj_col, adj_val);
    k3_agg <<<dim3(B_, 16), 256>>>(neighbors, gcn_b);
    k4_gx  <<<148, 320>>>(w_ih, b_ih);
    k5_gru <<<B_, 320>>>(w_hh, b_hh, fc1_w, fc1_b, out);
}

// round 3
// speedup vs baseline: 1.1171x; 1.0008x over previous
#include <cuda_runtime.h>

#define B_ 128
#define N_ 1024
#define E_ 16384
#define ENTITY_ 100000
#define HID_ 100
#define G3 300

// Scratch (static __device__ per harness rules; no runtime allocation)
__device__ float g_T[ENTITY_ * HID_];        // emb_table @ gcn_w   (40MB)
__device__ float g_seq[B_ * N_ * HID_];      // GCN output          (52MB)
__device__ float g_GX[B_ * N_ * G3];         // seq @ w_ih^T + b_ih (157MB)
__device__ int   g_soff[B_ * (N_ + 1)];
__device__ int   g_scol[B_ * E_];
__device__ float g_sval[B_ * E_];

typedef unsigned long long u64;

__device__ __forceinline__ void ffma2(u64 &acc, u64 a, u64 b) {
    asm("fma.rn.f32x2 %0, %1, %2, %0;" : "+l"(acc) : "l"(a), "l"(b));
}
__device__ __forceinline__ u64 pk2(float lo, float hi) {
    u64 r; asm("mov.b64 %0, {%1, %2};" : "=l"(r) : "f"(lo), "f"(hi)); return r;
}
__device__ __forceinline__ float sum2(u64 v) {
    float lo, hi; asm("mov.b64 {%0, %1}, %2;" : "=f"(lo), "=f"(hi) : "l"(v)); return lo + hi;
}
__device__ __forceinline__ void cp4(void* s, const void* g) {
    unsigned a = (unsigned)__cvta_generic_to_shared(s);
    asm volatile("cp.async.ca.shared.global [%0], [%1], 4;" :: "r"(a), "l"(g));
}

// ---------------------------------------------------------------------------
// K1: T = emb_table @ gcn_w   [100000,100] @ [100,100]
// 3 k-thirds x 2 cols: thread = (q, j0<50) computes cols j0, j0+50 over
// k in [36q, 36q+36). xs rows padded to 112 floats (16B-aligned thirds).
// 192 threads, ~120 regs -> 2 blocks/SM.
// ---------------------------------------------------------------------------
__global__ __launch_bounds__(192) void k1_T(const float* __restrict__ emb,
                                            const float* __restrict__ gcn_w) {
    __shared__ __align__(16) float xs[64 * 112];
    __shared__ float ps[3][8][104];
    int tid = threadIdx.x;
    int q = tid >> 6;          // k-third 0/1/2
    int j0 = tid & 63;         // <50 active
    bool act = j0 < 50;
    int jA = j0, jB = j0 + 50;
    u64 wA[18], wB[18];
    if (act) {
        #pragma unroll
        for (int p = 0; p < 18; p++) {
            int k = 36 * q + 2 * p;
            float aL = (k < HID_) ? gcn_w[k * HID_ + jA] : 0.f;
            float aH = (k + 1 < HID_) ? gcn_w[(k + 1) * HID_ + jA] : 0.f;
            float bL = (k < HID_) ? gcn_w[k * HID_ + jB] : 0.f;
            float bH = (k + 1 < HID_) ? gcn_w[(k + 1) * HID_ + jB] : 0.f;
            wA[p] = pk2(aL, aH);
            wB[p] = pk2(bL, bH);
        }
    }
    int r0 = blockIdx.x * 64;
    int rows = min(64, ENTITY_ - r0);
    const float4* src = (const float4*)(emb + (size_t)r0 * HID_);
    for (int i = tid; i < 64 * 28; i += 192) {
        int m = i / 28, c = i % 28;
        float4 v = make_float4(0.f, 0.f, 0.f, 0.f);
        if (c < 25 && m < rows) v = src[m * 25 + c];
        *(float4*)(xs + m * 112 + c * 4) = v;
    }
    __syncthreads();
    for (int chunk = 0; chunk < 8; chunk++) {
        int m0 = chunk * 8;
        if (act) {
            u64 aA[8], aB[8];
            #pragma unroll
            for (int mm = 0; mm < 8; mm++) { aA[mm] = 0; aB[mm] = 0; }
            #pragma unroll
            for (int mm = 0; mm < 8; mm++) {
                const ulonglong2* xp = (const ulonglong2*)(xs + (m0 + mm) * 112 + 36 * q);
                #pragma unroll
                for (int c = 0; c < 9; c++) {
                    ulonglong2 hv = xp[c];
                    ffma2(aA[mm], wA[2 * c], hv.x);
                    ffma2(aA[mm], wA[2 * c + 1], hv.y);
                    ffma2(aB[mm], wB[2 * c], hv.x);
                    ffma2(aB[mm], wB[2 * c + 1], hv.y);
                }
            }
            #pragma unroll
            for (int mm = 0; mm < 8; mm++) {
                ps[q][mm][jA] = sum2(aA[mm]);
                ps[q][mm][jB] = sum2(aB[mm]);
            }
        }
        __syncthreads();
        for (int o = tid; o < 8 * HID_; o += 192) {
            int mm = o / HID_, j = o % HID_;
            int m = m0 + mm;
            if (m < rows)
                g_T[(size_t)(r0 + m) * HID_ + j] = ps[0][mm][j] + ps[1][mm][j] + ps[2][mm][j];
        }
        __syncthreads();
    }
}

// ---------------------------------------------------------------------------
// K2: per-batch counting sort of edges by row (histogram + scan + scatter)
// ---------------------------------------------------------------------------
__global__ __launch_bounds__(1024) void k2_sort(const int* __restrict__ row,
                                                const int* __restrict__ col,
                                                const float* __restrict__ val) {
    __shared__ int bins[N_];
    __shared__ int sA[N_];
    int b = blockIdx.x, tid = threadIdx.x;
    bins[tid] = 0;
    __syncthreads();
    const int* rb = row + b * E_;
    const int* cb = col + b * E_;
    const float* vb = val + b * E_;
    for (int e = tid; e < E_; e += 1024) atomicAdd(&bins[rb[e]], 1);
    __syncthreads();
    int cnt = bins[tid];
    sA[tid] = cnt;
    __syncthreads();
    for (int off = 1; off < N_; off <<= 1) {
        int t = (tid >= off) ? sA[tid - off] : 0;
        __syncthreads();
        sA[tid] += t;
        __syncthreads();
    }
    int excl = sA[tid] - cnt;
    g_soff[b * (N_ + 1) + tid] = excl;
    if (tid == 0) g_soff[b * (N_ + 1) + N_] = E_;
    bins[tid] = excl;
    __syncthreads();
    for (int e = tid; e < E_; e += 1024) {
        int r = rb[e];
        int pos = atomicAdd(&bins[r], 1);
        g_scol[b * E_ + pos] = cb[e];
        g_sval[b * E_ + pos] = vb[e];
    }
}

// ---------------------------------------------------------------------------
// K3: seq[b,r,:] = sum_e val * T[neighbors[b, col_e], :] + gcn_b
// one warp per (b, row); 4-edge unroll (MLP=16)
// ---------------------------------------------------------------------------
__global__ __launch_bounds__(256) void k3_agg(const int* __restrict__ nbr,
                                              const float* __restrict__ gcn_b) {
    int b = blockIdx.x;
    int rbase = blockIdx.y * 64;
    int warp = threadIdx.x >> 5, lane = threadIdx.x & 31;
    const int* sc = g_scol + b * E_;
    const float* sv = g_sval + b * E_;
    const int* nb = nbr + b * N_;
    for (int r = rbase + warp; r < rbase + 64; r += 8) {
        int beg = g_soff[b * (N_ + 1) + r], end = g_soff[b * (N_ + 1) + r + 1];
        float a0 = 0.f, a1 = 0.f, a2 = 0.f, a3 = 0.f;
        float c0 = 0.f, c1 = 0.f, c2 = 0.f, c3 = 0.f;
        for (int ch = beg; ch < end; ch += 32) {
            int e = ch + lane;
            int c = 0; float v = 0.f;
            if (e < end) { c = sc[e]; v = sv[e]; }
            int ent = nb[c];
            int cnt = min(32, end - ch);
            int i = 0;
            for (; i + 3 < cnt; i += 4) {
                int e0 = __shfl_sync(0xffffffffu, ent, i);
                int e1 = __shfl_sync(0xffffffffu, ent, i + 1);
                int e2 = __shfl_sync(0xffffffffu, ent, i + 2);
                int e3 = __shfl_sync(0xffffffffu, ent, i + 3);
                float v0 = __shfl_sync(0xffffffffu, v, i);
                float v1 = __shfl_sync(0xffffffffu, v, i + 1);
                float v2 = __shfl_sync(0xffffffffu, v, i + 2);
                float v3 = __shfl_sync(0xffffffffu, v, i + 3);
                const float* t0 = g_T + (size_t)e0 * HID_;
                const float* t1 = g_T + (size_t)e1 * HID_;
                const float* t2 = g_T + (size_t)e2 * HID_;
                const float* t3 = g_T + (size_t)e3 * HID_;
                float x00 = t0[lane], x01 = t0[32 + lane], x02 = t0[64 + lane], x03 = t0[96 + (lane & 3)];
                float x10 = t1[lane], x11 = t1[32 + lane], x12 = t1[64 + lane], x13 = t1[96 + (lane & 3)];
                float x20 = t2[lane], x21 = t2[32 + lane], x22 = t2[64 + lane], x23 = t2[96 + (lane & 3)];
                float x30 = t3[lane], x31 = t3[32 + lane], x32 = t3[64 + lane], x33 = t3[96 + (lane & 3)];
                a0 += v0 * x00; a1 += v0 * x01; a2 += v0 * x02; a3 += v0 * x03;
                c0 += v1 * x10; c1 += v1 * x11; c2 += v1 * x12; c3 += v1 * x13;
                a0 += v2 * x20; a1 += v2 * x21; a2 += v2 * x22; a3 += v2 * x23;
                c0 += v3 * x30; c1 += v3 * x31; c2 += v3 * x32; c3 += v3 * x33;
            }
            for (; i < cnt; i++) {
                int e0 = __shfl_sync(0xffffffffu, ent, i);
                float v0 = __shfl_sync(0xffffffffu, v, i);
                const float* t0 = g_T + (size_t)e0 * HID_;
                a0 += v0 * t0[lane];
                a1 += v0 * t0[32 + lane];
                a2 += v0 * t0[64 + lane];
                a3 += v0 * t0[96 + (lane & 3)];
            }
        }
        float* o = g_seq + (size_t)(b * N_ + r) * HID_;
        o[lane]      = a0 + c0 + gcn_b[lane];
        o[32 + lane] = a1 + c1 + gcn_b[32 + lane];
        o[64 + lane] = a2 + c2 + gcn_b[64 + lane];
        if (lane < 4) o[96 + lane] = a3 + c3 + gcn_b[96 + lane];
    }
}

// ---------------------------------------------------------------------------
// K4: GX = seq @ w_ih^T + b_ih   [131072,100] @ [100,300]^T
// 3 k-thirds x 2 cols: thread = (q, j0<150) computes cols j0, j0+150 over
// k in [36q, 36q+36). xs rows padded to 112 floats. 480 threads -> 15 warps.
// ---------------------------------------------------------------------------
__global__ __launch_bounds__(480) void k4_gx(const float* __restrict__ w_ih,
                                             const float* __restrict__ b_ih) {
    __shared__ __align__(16) float xs[64 * 112];
    __shared__ float ps[3][8][304];
    __shared__ float bs[G3];
    int tid = threadIdx.x;
    int q = tid / 160;         // k-third
    int j0 = tid % 160;        // <150 active
    bool act = j0 < 150;
    int jA = j0, jB = j0 + 150;
    u64 wA[18], wB[18];
    if (act) {
        #pragma unroll
        for (int p = 0; p < 18; p++) {
            int k = 36 * q + 2 * p;
            float aL = (k < HID_) ? w_ih[jA * HID_ + k] : 0.f;
            float aH = (k + 1 < HID_) ? w_ih[jA * HID_ + k + 1] : 0.f;
            float bL = (k < HID_) ? w_ih[jB * HID_ + k] : 0.f;
            float bH = (k + 1 < HID_) ? w_ih[jB * HID_ + k + 1] : 0.f;
            wA[p] = pk2(aL, aH);
            wB[p] = pk2(bL, bH);
        }
    }
    for (int i = tid; i < G3; i += 480) bs[i] = b_ih[i];
    for (int tile = blockIdx.x; tile < 2048; tile += gridDim.x) {
        __syncthreads();
        const float4* src = (const float4*)(g_seq + (size_t)tile * 64 * HID_);
        for (int i = tid; i < 64 * 28; i += 480) {
            int m = i / 28, c = i % 28;
            float4 v = make_float4(0.f, 0.f, 0.f, 0.f);
            if (c < 25) v = src[m * 25 + c];
            *(float4*)(xs + m * 112 + c * 4) = v;
        }
        __syncthreads();
        for (int chunk = 0; chunk < 8; chunk++) {
            int m0 = chunk * 8;
            if (act) {
                u64 aA[8], aB[8];
                #pragma unroll
                for (int mm = 0; mm < 8; mm++) { aA[mm] = 0; aB[mm] = 0; }
                #pragma unroll
                for (int mm = 0; mm < 8; mm++) {
                    const ulonglong2* xp = (const ulonglong2*)(xs + (m0 + mm) * 112 + 36 * q);
                    #pragma unroll
                    for (int c = 0; c < 9; c++) {
                        ulonglong2 hv = xp[c];
                        ffma2(aA[mm], wA[2 * c], hv.x);
                        ffma2(aA[mm], wA[2 * c + 1], hv.y);
                        ffma2(aB[mm], wB[2 * c], hv.x);
                        ffma2(aB[mm], wB[2 * c + 1], hv.y);
                    }
                }
                #pragma unroll
                for (int mm = 0; mm < 8; mm++) {
                    ps[q][mm][jA] = sum2(aA[mm]);
                    ps[q][mm][jB] = sum2(aB[mm]);
                }
            }
            __syncthreads();
            float* ob = g_GX + ((size_t)tile * 64 + m0) * G3;
            for (int o = tid; o < 8 * G3; o += 480) {
                int mm = o / G3, j = o % G3;
                ob[mm * G3 + j] = ps[0][mm][j] + ps[1][mm][j] + ps[2][mm][j] + bs[j];
            }
            __syncthreads();
        }
    }
}

// ---------------------------------------------------------------------------
// K5: GRU recurrence, one block per batch element; fast MUFU activations.
// ---------------------------------------------------------------------------
__global__ __launch_bounds__(320) void k5_gru(const float* __restrict__ w_hh,
                                              const float* __restrict__ b_hh,
                                              const float* __restrict__ fc1_w,
                                              const float* __restrict__ fc1_b,
                                              float* __restrict__ out) {
    __shared__ __align__(16) float hbuf[2][128];
    __shared__ float ghs[G3];
    __shared__ float ring[8][G3];
    int b = blockIdx.x, tid = threadIdx.x;
    int j = tid;
    bool act = j < G3;
    u64 w2[50];
    float bhh = 0.f;
    if (act) {
        const u64* wp = (const u64*)(w_hh + j * HID_);
        #pragma unroll
        for (int p = 0; p < 50; p++) w2[p] = wp[p];
        bhh = b_hh[j];
    }
    if (tid < 128) { hbuf[0][tid] = 0.f; hbuf[1][tid] = 0.f; }
    const float* gxb = g_GX + (size_t)b * N_ * G3;
    #pragma unroll
    for (int p = 0; p < 4; p++) {
        if (act) cp4(&ring[p][j], gxb + p * G3 + j);
        asm volatile("cp.async.commit_group;");
    }
    for (int t = 0; t < N_; t++) {
        asm volatile("cp.async.wait_group 3;");
        __syncthreads();                         // stage t data + new h visible
        int pf = t + 4;
        if (act && pf < N_) cp4(&ring[pf & 7][j], gxb + (size_t)pf * G3 + j);
        asm volatile("cp.async.commit_group;");
        const float* hc = hbuf[t & 1];
        if (act) {
            const ulonglong2* hp = (const ulonglong2*)hc;
            u64 a0 = 0, a1 = 0, a2 = 0, a3 = 0;
            #pragma unroll
            for (int qq = 0; qq < 25; qq++) {
                ulonglong2 hv = hp[qq];
                if (qq & 1) { ffma2(a2, w2[2 * qq], hv.x); ffma2(a3, w2[2 * qq + 1], hv.y); }
                else        { ffma2(a0, w2[2 * qq], hv.x); ffma2(a1, w2[2 * qq + 1], hv.y); }
            }
            ghs[j] = sum2(a0) + sum2(a1) + sum2(a2) + sum2(a3) + bhh;
        }
        __syncthreads();                         // ghs ready
        if (j < HID_) {
            int st = t & 7;
            float gxr = ring[st][j], gxz = ring[st][HID_ + j], gxn = ring[st][2 * HID_ + j];
            float hr = ghs[j], hz = ghs[HID_ + j], hn = ghs[2 * HID_ + j];
            float er = __expf(-(gxr + hr));
            float r = __fdividef(1.f, 1.f + er);
            float ez = __expf(-(gxz + hz));
            float z = __fdividef(1.f, 1.f + ez);
            float an = gxn + r * hn;
            float e2 = __expf(2.f * an);
            float n = 1.f - __fdividef(2.f, e2 + 1.f);
            hbuf[(t + 1) & 1][j] = (1.f - z) * n + z * hc[j];
        }
    }
    __syncthreads();
    if (j < HID_) {
        const float* hf = hbuf[0];               // final h (t=1023 wrote buf 0)
        float acc = fc1_b[j];
        const float* wr = fc1_w + j * HID_;
        #pragma unroll
        for (int k = 0; k < HID_; k++) acc += hf[k] * wr[k];
        out[b * HID_ + j] = fmaxf(acc, 0.f);
    }
}

// ---------------------------------------------------------------------------
extern "C" void kernel_launch(void* const* d_in, const int* in_sizes, int n_in,
                              void* d_out, int out_size) {
    const int*   neighbors = (const int*)d_in[0];
    const int*   adj_row   = (const int*)d_in[1];
    const int*   adj_col   = (const int*)d_in[2];
    const float* adj_val   = (const float*)d_in[3];
    const float* emb       = (const float*)d_in[4];
    const float* gcn_w     = (const float*)d_in[5];
    const float* gcn_b     = (const float*)d_in[6];
    const float* w_ih      = (const float*)d_in[7];
    const float* w_hh      = (const float*)d_in[8];
    const float* b_ih      = (const float*)d_in[9];
    const float* b_hh      = (const float*)d_in[10];
    const float* fc1_w     = (const float*)d_in[11];
    const float* fc1_b     = (const float*)d_in[12];
    float* out = (float*)d_out;

    k1_T   <<<(ENTITY_ + 63) / 64, 192>>>(emb, gcn_w);
    k2_sort<<<B_, 1024>>>(adj_row, adj_col, adj_val);
    k3_agg <<<dim3(B_, 16), 256>>>(neighbors, gcn_b);
    k4_gx  <<<148, 480>>>(w_ih, b_ih);
    k5_gru <<<B_, 320>>>(w_hh, b_hh, fc1_w, fc1_b, out);
}

// round 5
// speedup vs baseline: 1.3233x; 1.1846x over previous
#include <cuda_runtime.h>

#define B_ 128
#define N_ 1024
#define E_ 16384
#define ENTITY_ 100000
#define HID_ 100
#define G3 300

// Scratch (static __device__ per harness rules; no runtime allocation)
__device__ float g_T[ENTITY_ * HID_];        // emb_table @ gcn_w   (40MB)
__device__ float g_seq[B_ * N_ * HID_];      // GCN output          (52MB)
__device__ float g_GX[B_ * N_ * G3];         // seq @ w_ih^T + b_ih (157MB)
__device__ int   g_soff[B_ * (N_ + 1)];
__device__ int   g_scol[B_ * E_];
__device__ float g_sval[B_ * E_];

typedef unsigned long long u64;
typedef unsigned int u32;

__device__ __forceinline__ void ffma2(u64 &acc, u64 a, u64 b) {
    asm("fma.rn.f32x2 %0, %1, %2, %0;" : "+l"(acc) : "l"(a), "l"(b));
}
__device__ __forceinline__ float sum2(u64 v) {
    float lo, hi; asm("mov.b64 {%0, %1}, %2;" : "=f"(lo), "=f"(hi) : "l"(v)); return lo + hi;
}
__device__ __forceinline__ void cp4(void* s, const void* g) {
    unsigned a = (unsigned)__cvta_generic_to_shared(s);
    asm volatile("cp.async.ca.shared.global [%0], [%1], 4;" :: "r"(a), "l"(g));
}
__device__ __forceinline__ u32 f2tf(float x) {
    u32 r; asm("cvt.rna.tf32.f32 %0, %1;" : "=r"(r) : "f"(x)); return r;
}
__device__ __forceinline__ void mma1688(float c[4], u32 a0, u32 a1, u32 a2, u32 a3,
                                        u32 b0, u32 b1) {
    asm("mma.sync.aligned.m16n8k8.row.col.f32.tf32.tf32.f32 "
        "{%0,%1,%2,%3}, {%4,%5,%6,%7}, {%8,%9}, {%0,%1,%2,%3};"
        : "+f"(c[0]), "+f"(c[1]), "+f"(c[2]), "+f"(c[3])
        : "r"(a0), "r"(a1), "r"(a2), "r"(a3), "r"(b0), "r"(b1));
}

// ---------------------------------------------------------------------------
// tf32 GEMM: out[M x NOUT] = X[M x 100] @ W^T (+ bias if HASB)
// W given [NOUT x 100] row-major if !TRANSW, or [100 x NOUT] k-major if TRANSW.
// 512 threads = 16 warps (4 m-pos x 4 n-groups); block tile 64 x NP,
// NP = 32*NFR. W staged once in smem as [n][k], stride KP=108 (bank =
// 12g+tig, conflict-free). K=100 padded to 104 -> 13 k-steps of m16n8k8.
// ---------------------------------------------------------------------------
#define KP 108

template<int NP, int NFR, int NOUT, bool TRANSW, bool USE_GSEQ, bool HASB>
__global__ __launch_bounds__(512) void gemm_tf32(const float* __restrict__ Xparam,
                                                 const float* __restrict__ Wg,
                                                 const float* __restrict__ bias,
                                                 int Mtotal, int ntiles) {
    extern __shared__ u32 smem[];
    u32* Ws = smem;                                  // NP * KP
    u32* Xs = smem + NP * KP;                        // 64 * KP
    float* bs = (float*)(smem + NP * KP + 64 * KP);  // NP

    const float* X = USE_GSEQ ? (const float*)g_seq : Xparam;
    float* out = USE_GSEQ ? (float*)g_GX : (float*)g_T;

    int tid = threadIdx.x;
    int w = tid >> 5, lane = tid & 31;
    int mw = w & 3, nw = w >> 2;
    int g = lane >> 2, tig = lane & 3;
    int colbase = nw * NFR * 8;

    // --- Stage W (once per block) ---
    if (TRANSW) {
        for (int i = tid; i < NP * KP; i += 512) {
            int n = i / KP, k = i % KP;
            float v = (n < NOUT && k < HID_) ? Wg[k * NOUT + n] : 0.f;
            Ws[n * KP + k] = f2tf(v);
        }
    } else {
        for (int i = tid; i < NP * 27; i += 512) {
            int n = i / 27, c = i % 27;
            float4 v = make_float4(0.f, 0.f, 0.f, 0.f);
            if (n < NOUT && c < 25) v = ((const float4*)Wg)[n * 25 + c];
            u32* d = Ws + n * KP + c * 4;
            d[0] = f2tf(v.x); d[1] = f2tf(v.y); d[2] = f2tf(v.z); d[3] = f2tf(v.w);
        }
    }
    for (int i = tid; i < NP; i += 512)
        bs[i] = (HASB && i < NOUT) ? bias[i] : 0.f;
    __syncthreads();

    for (int tile = blockIdx.x; tile < ntiles; tile += gridDim.x) {
        __syncthreads();   // previous tile's Xs fully consumed
        for (int i = tid; i < 64 * 27; i += 512) {
            int m = i / 27, c = i % 27;
            int row = tile * 64 + m;
            float4 v = make_float4(0.f, 0.f, 0.f, 0.f);
            if (row < Mtotal && c < 25) v = ((const float4*)X)[(size_t)row * 25 + c];
            u32* d = Xs + m * KP + c * 4;
            d[0] = f2tf(v.x); d[1] = f2tf(v.y); d[2] = f2tf(v.z); d[3] = f2tf(v.w);
        }
        __syncthreads();

        float c[NFR][4];
        #pragma unroll
        for (int f = 0; f < NFR; f++) { c[f][0] = 0.f; c[f][1] = 0.f; c[f][2] = 0.f; c[f][3] = 0.f; }

        const u32* Xb = Xs + (mw * 16) * KP;
        #pragma unroll
        for (int ks = 0; ks < 13; ks++) {
            int k0 = ks * 8;
            u32 a0 = Xb[g * KP + k0 + tig];
            u32 a1 = Xb[(g + 8) * KP + k0 + tig];
            u32 a2 = Xb[g * KP + k0 + tig + 4];
            u32 a3 = Xb[(g + 8) * KP + k0 + tig + 4];
            #pragma unroll
            for (int f = 0; f < NFR; f++) {
                const u32* wp = Ws + (colbase + 8 * f + g) * KP + k0 + tig;
                u32 b0 = wp[0];
                u32 b1 = wp[4];
                mma1688(c[f], a0, a1, a2, a3, b0, b1);
            }
        }

        int r0 = tile * 64 + mw * 16 + g;
        #pragma unroll
        for (int f = 0; f < NFR; f++) {
            int col = colbase + 8 * f + 2 * tig;
            if (r0 < Mtotal) {
                if (col < NOUT)     out[(size_t)r0 * NOUT + col]     = c[f][0] + bs[col];
                if (col + 1 < NOUT) out[(size_t)r0 * NOUT + col + 1] = c[f][1] + bs[col + 1];
            }
            if (r0 + 8 < Mtotal) {
                if (col < NOUT)     out[(size_t)(r0 + 8) * NOUT + col]     = c[f][2] + bs[col];
                if (col + 1 < NOUT) out[(size_t)(r0 + 8) * NOUT + col + 1] = c[f][3] + bs[col + 1];
            }
        }
    }
}

#define K1_SMEM ((128 * KP + 64 * KP) * 4 + 128 * 4)
#define K4_SMEM ((320 * KP + 64 * KP) * 4 + 320 * 4)

// ---------------------------------------------------------------------------
// K2: per-batch counting sort of edges by row (histogram + scan + scatter)
// ---------------------------------------------------------------------------
__global__ __launch_bounds__(1024) void k2_sort(const int* __restrict__ row,
                                                const int* __restrict__ col,
                                                const float* __restrict__ val) {
    __shared__ int bins[N_];
    __shared__ int sA[N_];
    int b = blockIdx.x, tid = threadIdx.x;
    bins[tid] = 0;
    __syncthreads();
    const int* rb = row + b * E_;
    const int* cb = col + b * E_;
    const float* vb = val + b * E_;
    for (int e = tid; e < E_; e += 1024) atomicAdd(&bins[rb[e]], 1);
    __syncthreads();
    int cnt = bins[tid];
    sA[tid] = cnt;
    __syncthreads();
    for (int off = 1; off < N_; off <<= 1) {
        int t = (tid >= off) ? sA[tid - off] : 0;
        __syncthreads();
        sA[tid] += t;
        __syncthreads();
    }
    int excl = sA[tid] - cnt;
    g_soff[b * (N_ + 1) + tid] = excl;
    if (tid == 0) g_soff[b * (N_ + 1) + N_] = E_;
    bins[tid] = excl;
    __syncthreads();
    for (int e = tid; e < E_; e += 1024) {
        int r = rb[e];
        int pos = atomicAdd(&bins[r], 1);
        g_scol[b * E_ + pos] = cb[e];
        g_sval[b * E_ + pos] = vb[e];
    }
}

// ---------------------------------------------------------------------------
// K3: seq[b,r,:] = sum_e val * T[neighbors[b, col_e], :] + gcn_b
// ---------------------------------------------------------------------------
__global__ __launch_bounds__(256) void k3_agg(const int* __restrict__ nbr,
                                              const float* __restrict__ gcn_b) {
    int b = blockIdx.x;
    int rbase = blockIdx.y * 64;
    int warp = threadIdx.x >> 5, lane = threadIdx.x & 31;
    const int* sc = g_scol + b * E_;
    const float* sv = g_sval + b * E_;
    const int* nb = nbr + b * N_;
    for (int r = rbase + warp; r < rbase + 64; r += 8) {
        int beg = g_soff[b * (N_ + 1) + r], end = g_soff[b * (N_ + 1) + r + 1];
        float a0 = 0.f, a1 = 0.f, a2 = 0.f, a3 = 0.f;
        float c0 = 0.f, c1 = 0.f, c2 = 0.f, c3 = 0.f;
        for (int ch = beg; ch < end; ch += 32) {
            int e = ch + lane;
            int c = 0; float v = 0.f;
            if (e < end) { c = sc[e]; v = sv[e]; }
            int ent = nb[c];
            int cnt = min(32, end - ch);
            int i = 0;
            for (; i + 3 < cnt; i += 4) {
                int e0 = __shfl_sync(0xffffffffu, ent, i);
                int e1 = __shfl_sync(0xffffffffu, ent, i + 1);
                int e2 = __shfl_sync(0xffffffffu, ent, i + 2);
                int e3 = __shfl_sync(0xffffffffu, ent, i + 3);
                float v0 = __shfl_sync(0xffffffffu, v, i);
                float v1 = __shfl_sync(0xffffffffu, v, i + 1);
                float v2 = __shfl_sync(0xffffffffu, v, i + 2);
                float v3 = __shfl_sync(0xffffffffu, v, i + 3);
                const float* t0 = g_T + (size_t)e0 * HID_;
                const float* t1 = g_T + (size_t)e1 * HID_;
                const float* t2 = g_T + (size_t)e2 * HID_;
                const float* t3 = g_T + (size_t)e3 * HID_;
                float x00 = t0[lane], x01 = t0[32 + lane], x02 = t0[64 + lane], x03 = t0[96 + (lane & 3)];
                float x10 = t1[lane], x11 = t1[32 + lane], x12 = t1[64 + lane], x13 = t1[96 + (lane & 3)];
                float x20 = t2[lane], x21 = t2[32 + lane], x22 = t2[64 + lane], x23 = t2[96 + (lane & 3)];
                float x30 = t3[lane], x31 = t3[32 + lane], x32 = t3[64 + lane], x33 = t3[96 + (lane & 3)];
                a0 += v0 * x00; a1 += v0 * x01; a2 += v0 * x02; a3 += v0 * x03;
                c0 += v1 * x10; c1 += v1 * x11; c2 += v1 * x12; c3 += v1 * x13;
                a0 += v2 * x20; a1 += v2 * x21; a2 += v2 * x22; a3 += v2 * x23;
                c0 += v3 * x30; c1 += v3 * x31; c2 += v3 * x32; c3 += v3 * x33;
            }
            for (; i < cnt; i++) {
                int e0 = __shfl_sync(0xffffffffu, ent, i);
                float v0 = __shfl_sync(0xffffffffu, v, i);
                const float* t0 = g_T + (size_t)e0 * HID_;
                a0 += v0 * t0[lane];
                a1 += v0 * t0[32 + lane];
                a2 += v0 * t0[64 + lane];
                a3 += v0 * t0[96 + (lane & 3)];
            }
        }
        float* o = g_seq + (size_t)(b * N_ + r) * HID_;
        o[lane]      = a0 + c0 + gcn_b[lane];
        o[32 + lane] = a1 + c1 + gcn_b[32 + lane];
        o[64 + lane] = a2 + c2 + gcn_b[64 + lane];
        if (lane < 4) o[96 + lane] = a3 + c3 + gcn_b[96 + lane];
    }
}

// ---------------------------------------------------------------------------
// K5: GRU recurrence, one block per batch element; fast MUFU activations.
// ---------------------------------------------------------------------------
__global__ __launch_bounds__(320) void k5_gru(const float* __restrict__ w_hh,
                                              const float* __restrict__ b_hh,
                                              const float* __restrict__ fc1_w,
                                              const float* __restrict__ fc1_b,
                                              float* __restrict__ out) {
    __shared__ __align__(16) float hbuf[2][128];
    __shared__ float ghs[G3];
    __shared__ float ring[8][G3];
    int b = blockIdx.x, tid = threadIdx.x;
    int j = tid;
    bool act = j < G3;
    u64 w2[50];
    float bhh = 0.f;
    if (act) {
        const u64* wp = (const u64*)(w_hh + j * HID_);
        #pragma unroll
        for (int p = 0; p < 50; p++) w2[p] = wp[p];
        bhh = b_hh[j];
    }
    if (tid < 128) { hbuf[0][tid] = 0.f; hbuf[1][tid] = 0.f; }
    const float* gxb = g_GX + (size_t)b * N_ * G3;
    #pragma unroll
    for (int p = 0; p < 4; p++) {
        if (act) cp4(&ring[p][j], gxb + p * G3 + j);
        asm volatile("cp.async.commit_group;");
    }
    for (int t = 0; t < N_; t++) {
        asm volatile("cp.async.wait_group 3;");
        __syncthreads();
        int pf = t + 4;
        if (act && pf < N_) cp4(&ring[pf & 7][j], gxb + (size_t)pf * G3 + j);
        asm volatile("cp.async.commit_group;");
        const float* hc = hbuf[t & 1];
        if (act) {
            const ulonglong2* hp = (const ulonglong2*)hc;
            u64 a0 = 0, a1 = 0, a2 = 0, a3 = 0;
            #pragma unroll
            for (int qq = 0; qq < 25; qq++) {
                ulonglong2 hv = hp[qq];
                if (qq & 1) { ffma2(a2, w2[2 * qq], hv.x); ffma2(a3, w2[2 * qq + 1], hv.y); }
                else        { ffma2(a0, w2[2 * qq], hv.x); ffma2(a1, w2[2 * qq + 1], hv.y); }
            }
            ghs[j] = sum2(a0) + sum2(a1) + sum2(a2) + sum2(a3) + bhh;
        }
        __syncthreads();
        if (j < HID_) {
            int st = t & 7;
            float gxr = ring[st][j], gxz = ring[st][HID_ + j], gxn = ring[st][2 * HID_ + j];
            float hr = ghs[j], hz = ghs[HID_ + j], hn = ghs[2 * HID_ + j];
            float er = __expf(-(gxr + hr));
            float r = __fdividef(1.f, 1.f + er);
            float ez = __expf(-(gxz + hz));
            float z = __fdividef(1.f, 1.f + ez);
            float an = gxn + r * hn;
            float e2 = __expf(2.f * an);
            float n = 1.f - __fdividef(2.f, e2 + 1.f);
            hbuf[(t + 1) & 1][j] = (1.f - z) * n + z * hc[j];
        }
    }
    __syncthreads();
    if (j < HID_) {
        const float* hf = hbuf[0];
        float acc = fc1_b[j];
        const float* wr = fc1_w + j * HID_;
        #pragma unroll
        for (int k = 0; k < HID_; k++) acc += hf[k] * wr[k];
        out[b * HID_ + j] = fmaxf(acc, 0.f);
    }
}

// ---------------------------------------------------------------------------
extern "C" void kernel_launch(void* const* d_in, const int* in_sizes, int n_in,
                              void* d_out, int out_size) {
    const int*   neighbors = (const int*)d_in[0];
    const int*   adj_row   = (const int*)d_in[1];
    const int*   adj_col   = (const int*)d_in[2];
    const float* adj_val   = (const float*)d_in[3];
    const float* emb       = (const float*)d_in[4];
    const float* gcn_w     = (const float*)d_in[5];
    const float* gcn_b     = (const float*)d_in[6];
    const float* w_ih      = (const float*)d_in[7];
    const float* w_hh      = (const float*)d_in[8];
    const float* b_ih      = (const float*)d_in[9];
    const float* b_hh      = (const float*)d_in[10];
    const float* fc1_w     = (const float*)d_in[11];
    const float* fc1_b     = (const float*)d_in[12];
    float* out = (float*)d_out;

    cudaFuncSetAttribute(gemm_tf32<128, 4, 100, true, false, false>,
                         cudaFuncAttributeMaxDynamicSharedMemorySize, K1_SMEM);
    cudaFuncSetAttribute(gemm_tf32<320, 10, 300, false, true, true>,
                         cudaFuncAttributeMaxDynamicSharedMemorySize, K4_SMEM);

    // K1: T = emb @ gcn_w  (no bias — gcn_b is added in K3 after the spmm)
    gemm_tf32<128, 4, 100, true, false, false><<<148, 512, K1_SMEM>>>(
        emb, gcn_w, gcn_b, ENTITY_, (ENTITY_ + 63) / 64);
    k2_sort<<<B_, 1024>>>(adj_row, adj_col, adj_val);
    k3_agg <<<dim3(B_, 16), 256>>>(neighbors, gcn_b);
    // K4: GX = seq @ w_ih^T + b_ih
    gemm_tf32<320, 10, 300, false, true, true><<<148, 512, K4_SMEM>>>(
        nullptr, w_ih, b_ih, B_ * N_, (B_ * N_ + 63) / 64);
    k5_gru <<<B_, 320>>>(w_hh, b_hh, fc1_w, fc1_b, out);
}